// round 1
// baseline (speedup 1.0000x reference)
#include <cuda_runtime.h>
#include <math.h>

#define BATCH 16
#define CH 3
#define IMGSZ 384
#define PSZ 16
#define HP (IMGSZ/PSZ)          /* 24 */
#define DIM 384
#define DEPTH 6
#define HEADS 6
#define DH 64
#define INNER 384
#define MLP 1536
#define NPATCH 576
#define PATCH_DIM 768
#define SEQ 1153
#define TOK (BATCH*SEQ)         /* 18448 */

// ---------------- scratch (device globals: allocation-free rule) -------------
__device__ float g_x[(size_t)TOK*DIM];
__device__ float g_h[(size_t)TOK*DIM];
__device__ float g_qkv[(size_t)TOK*3*INNER];
__device__ float g_attn[(size_t)BATCH*HEADS*SEQ*SEQ];   // ~510 MB
__device__ float g_o[(size_t)TOK*INNER];
__device__ float g_ff[(size_t)TOK*MLP];
__device__ float g_patch[(size_t)BATCH*2*NPATCH*PATCH_DIM];

// ---------------- generic tiled fp32 GEMM -----------------------------------
// C[M,N] = act(alpha * A@B (+bias)) (+residual)
// TRANSB=false: B is [K,N] row-major (ldb). TRANSB=true: B is [N,K] (ldb), C=A@B^T.
// Batched via grid.z: bz -> (outer = bz/innerCount, inner = bz%innerCount),
// each operand offset by outer*Outer + inner*Inner element strides.
template<int BN, int TN, bool TRANSB>
__global__ __launch_bounds__(256) void gemm_kernel(
    const float* __restrict__ A, const float* __restrict__ Bm, float* __restrict__ C,
    int M, int N, int K, int lda, int ldb, int ldc,
    int innerCount,
    long long aOuter, long long aInner,
    long long bOuter, long long bInner,
    long long cOuter, long long cInner,
    const float* __restrict__ bias,
    const float* __restrict__ resid, int ldr,
    float alpha, int act)
{
    constexpr int BM = 128, BK = 8, TM = 8;
    constexpr int NT = (BM/TM) * (BN/TN);   // 256 for both configs used
    __shared__ float As[BK][BM];
    __shared__ float Bs[BK][BN];

    const int bz = blockIdx.z;
    const int ob = bz / innerCount, ib = bz % innerCount;
    A  += ob*aOuter + ib*aInner;
    Bm += ob*bOuter + ib*bInner;
    C  += ob*cOuter + ib*cInner;
    const float* R = resid;
    if (R) R += ob*cOuter + ib*cInner;   // residual shares C's addressing in all uses

    const int m0 = blockIdx.y * BM;
    const int n0 = blockIdx.x * BN;
    const int tid = threadIdx.x;
    const int trow = (tid / (BN/TN)) * TM;
    const int tcol = (tid % (BN/TN)) * TN;

    float acc[TM][TN];
    #pragma unroll
    for (int i = 0; i < TM; i++)
        #pragma unroll
        for (int j = 0; j < TN; j++) acc[i][j] = 0.f;

    for (int k0 = 0; k0 < K; k0 += BK) {
        // load A tile (BM x BK)
        #pragma unroll
        for (int i = tid; i < BM*BK; i += NT) {
            int m = i / BK, k = i % BK;
            float v = 0.f;
            if (m0 + m < M && k0 + k < K) v = A[(long long)(m0+m)*lda + (k0+k)];
            As[k][m] = v;
        }
        // load B tile (BK x BN)
        #pragma unroll
        for (int i = tid; i < BK*BN; i += NT) {
            if (!TRANSB) {
                int k = i / BN, n = i % BN;
                float v = 0.f;
                if (k0 + k < K && n0 + n < N) v = Bm[(long long)(k0+k)*ldb + (n0+n)];
                Bs[k][n] = v;
            } else {
                int n = i / BK, k = i % BK;
                float v = 0.f;
                if (n0 + n < N && k0 + k < K) v = Bm[(long long)(n0+n)*ldb + (k0+k)];
                Bs[k][n] = v;
            }
        }
        __syncthreads();
        #pragma unroll
        for (int k = 0; k < BK; k++) {
            float af[TM], bf[TN];
            #pragma unroll
            for (int i = 0; i < TM; i++) af[i] = As[k][trow+i];
            #pragma unroll
            for (int j = 0; j < TN; j++) bf[j] = Bs[k][tcol+j];
            #pragma unroll
            for (int i = 0; i < TM; i++)
                #pragma unroll
                for (int j = 0; j < TN; j++)
                    acc[i][j] = fmaf(af[i], bf[j], acc[i][j]);
        }
        __syncthreads();
    }

    #pragma unroll
    for (int i = 0; i < TM; i++) {
        int m = m0 + trow + i;
        if (m >= M) continue;
        #pragma unroll
        for (int j = 0; j < TN; j++) {
            int n = n0 + tcol + j;
            if (n >= N) continue;
            float v = acc[i][j] * alpha;
            if (bias) v += bias[n];
            if (act)  v = 0.5f * v * (1.f + erff(v * 0.70710678118654752440f));
            if (R)    v += R[(long long)m*ldr + n];
            C[(long long)m*ldc + n] = v;
        }
    }
}

// ---------------- patchify: img -> [b, t(0..1151), 768] ---------------------
__global__ void patchify_kernel(const float* __restrict__ before,
                                const float* __restrict__ after,
                                float* __restrict__ out)
{
    long long idx = (long long)blockIdx.x * blockDim.x + threadIdx.x;
    const long long total = (long long)BATCH * 2 * NPATCH * PATCH_DIM;
    if (idx >= total) return;
    int pd = (int)(idx % PATCH_DIM);
    long long tmp = idx / PATCH_DIM;
    int t = (int)(tmp % (2*NPATCH));
    int b = (int)(tmp / (2*NPATCH));
    const float* img = (t < NPATCH) ? before : after;
    int tt = t % NPATCH;
    int hh = tt / HP, ww = tt % HP;
    int c = pd % CH;
    int q = pd / CH;
    int p2 = q % PSZ, p1 = q / PSZ;
    out[idx] = img[((long long)b*CH + c)*IMGSZ*IMGSZ + (long long)(hh*PSZ + p1)*IMGSZ + (ww*PSZ + p2)];
}

// ---------------- assemble x = [cls | emb+pos | emb+pos] ---------------------
__global__ void assemble_kernel(const float* __restrict__ emb,
                                const float* __restrict__ pos,
                                const float* __restrict__ cls,
                                float* __restrict__ x)
{
    long long idx = (long long)blockIdx.x * blockDim.x + threadIdx.x;
    const long long total = (long long)TOK * DIM;
    if (idx >= total) return;
    int d = (int)(idx % DIM);
    long long tmp = idx / DIM;
    int s = (int)(tmp % SEQ);
    int b = (int)(tmp / SEQ);
    float v;
    if (s == 0) v = cls[d];
    else {
        int t = s - 1;
        v = emb[((long long)b*(2*NPATCH) + t)*DIM + d] + pos[(long long)(t % NPATCH)*DIM + d];
    }
    x[idx] = v;
}

// ---------------- LayerNorm (row of 384, 128 threads/row) --------------------
__global__ __launch_bounds__(128) void layernorm_kernel(
    const float* __restrict__ x, float* __restrict__ y,
    const float* __restrict__ g, const float* __restrict__ bta)
{
    long long row = blockIdx.x;
    const float* xr = x + row * DIM;
    int t = threadIdx.x;
    float v0 = xr[t], v1 = xr[t+128], v2 = xr[t+256];
    float s  = v0 + v1 + v2;
    float s2 = v0*v0 + v1*v1 + v2*v2;
    #pragma unroll
    for (int o = 16; o; o >>= 1) {
        s  += __shfl_xor_sync(0xffffffffu, s,  o);
        s2 += __shfl_xor_sync(0xffffffffu, s2, o);
    }
    __shared__ float sh[8];
    int w = t >> 5;
    if ((t & 31) == 0) { sh[w] = s; sh[4+w] = s2; }
    __syncthreads();
    s  = sh[0] + sh[1] + sh[2] + sh[3];
    s2 = sh[4] + sh[5] + sh[6] + sh[7];
    float mean = s * (1.f/DIM);
    float var  = s2 * (1.f/DIM) - mean*mean;
    float r = rsqrtf(var + 1e-5f);
    float* yr = y + row * DIM;
    yr[t]     = (v0 - mean)*r*g[t]     + bta[t];
    yr[t+128] = (v1 - mean)*r*g[t+128] + bta[t+128];
    yr[t+256] = (v2 - mean)*r*g[t+256] + bta[t+256];
}

// ---------------- row softmax over SEQ=1153 ----------------------------------
__global__ __launch_bounds__(256) void softmax_kernel(float* __restrict__ a)
{
    long long row = blockIdx.x;
    float* ar = a + row * (long long)SEQ;
    int t = threadIdx.x;
    float vals[5];
    float mx = -3.0e38f;
    #pragma unroll
    for (int i = 0; i < 5; i++) {
        int j = t + i*256;
        vals[i] = (j < SEQ) ? ar[j] : -3.0e38f;
        mx = fmaxf(mx, vals[i]);
    }
    __shared__ float sh[8];
    #pragma unroll
    for (int o = 16; o; o >>= 1) mx = fmaxf(mx, __shfl_xor_sync(0xffffffffu, mx, o));
    if ((t & 31) == 0) sh[t >> 5] = mx;
    __syncthreads();
    mx = fmaxf(fmaxf(fmaxf(sh[0],sh[1]),fmaxf(sh[2],sh[3])),
               fmaxf(fmaxf(sh[4],sh[5]),fmaxf(sh[6],sh[7])));
    __syncthreads();
    float s = 0.f;
    #pragma unroll
    for (int i = 0; i < 5; i++) {
        int j = t + i*256;
        vals[i] = (j < SEQ) ? expf(vals[i] - mx) : 0.f;
        s += vals[i];
    }
    #pragma unroll
    for (int o = 16; o; o >>= 1) s += __shfl_xor_sync(0xffffffffu, s, o);
    if ((t & 31) == 0) sh[t >> 5] = s;
    __syncthreads();
    s = sh[0]+sh[1]+sh[2]+sh[3]+sh[4]+sh[5]+sh[6]+sh[7];
    float inv = 1.f / s;
    #pragma unroll
    for (int i = 0; i < 5; i++) {
        int j = t + i*256;
        if (j < SEQ) ar[j] = vals[i] * inv;
    }
}

// ---------------- output: cls rows -------------------------------------------
__global__ void copyout_kernel(const float* __restrict__ x, float* __restrict__ out)
{
    int idx = blockIdx.x * blockDim.x + threadIdx.x;
    if (idx >= BATCH * DIM) return;
    int b = idx / DIM, d = idx % DIM;
    out[idx] = x[(long long)b*SEQ*DIM + d];
}

// ---------------- host orchestration -----------------------------------------
static inline void gemm_flat(const float* A, const float* Bm, float* C,
                             int M, int N, int K, int lda, int ldb, int ldc,
                             const float* bias, const float* resid, int ldr,
                             float alpha, int act)
{
    dim3 grid((N + 127) / 128, (M + 127) / 128, 1);
    gemm_kernel<128,8,false><<<grid, 256>>>(A, Bm, C, M, N, K, lda, ldb, ldc,
        1, 0, 0, 0, 0, 0, 0, bias, resid, ldr, alpha, act);
}

extern "C" void kernel_launch(void* const* d_in, const int* in_sizes, int n_in,
                              void* d_out, int out_size)
{
    const float* img_before = (const float*)d_in[0];
    const float* img_after  = (const float*)d_in[1];
    const float* patch_w    = (const float*)d_in[2];
    const float* patch_b    = (const float*)d_in[3];
    const float* pos_emb    = (const float*)d_in[4];
    const float* cls_tok    = (const float*)d_in[5];
    const float* ln1_g      = (const float*)d_in[6];
    const float* ln1_b      = (const float*)d_in[7];
    const float* w_qkv      = (const float*)d_in[8];
    const float* w_out      = (const float*)d_in[9];
    const float* b_out      = (const float*)d_in[10];
    const float* ln2_g      = (const float*)d_in[11];
    const float* ln2_b      = (const float*)d_in[12];
    const float* w_ff1      = (const float*)d_in[13];
    const float* b_ff1      = (const float*)d_in[14];
    const float* w_ff2      = (const float*)d_in[15];
    const float* b_ff2      = (const float*)d_in[16];
    float* out = (float*)d_out;

    static float *px=nullptr, *ph=nullptr, *pqkv=nullptr, *pattn=nullptr,
                 *po=nullptr, *pff=nullptr, *ppatch=nullptr;
    if (!px) {
        cudaGetSymbolAddress((void**)&px,    g_x);
        cudaGetSymbolAddress((void**)&ph,    g_h);
        cudaGetSymbolAddress((void**)&pqkv,  g_qkv);
        cudaGetSymbolAddress((void**)&pattn, g_attn);
        cudaGetSymbolAddress((void**)&po,    g_o);
        cudaGetSymbolAddress((void**)&pff,   g_ff);
        cudaGetSymbolAddress((void**)&ppatch,g_patch);
    }

    // ---- patch embedding ----
    {
        long long total = (long long)BATCH * 2 * NPATCH * PATCH_DIM;
        patchify_kernel<<<(unsigned)((total + 255) / 256), 256>>>(img_before, img_after, ppatch);
        // emb = patch @ patch_w + patch_b   -> reuse g_o as temp [B*1152, 384]
        gemm_flat(ppatch, patch_w, po, BATCH*2*NPATCH, DIM, PATCH_DIM,
                  PATCH_DIM, DIM, DIM, patch_b, nullptr, 0, 1.f, 0);
        long long tx = (long long)TOK * DIM;
        assemble_kernel<<<(unsigned)((tx + 255) / 256), 256>>>(po, pos_emb, cls_tok, px);
    }

    const float scale = 0.125f;   // DH^-0.5

    for (int i = 0; i < DEPTH; i++) {
        // ---- attention ----
        layernorm_kernel<<<TOK, 128>>>(px, ph, ln1_g + i*DIM, ln1_b + i*DIM);
        gemm_flat(ph, w_qkv + (long long)i*DIM*3*INNER, pqkv,
                  TOK, 3*INNER, DIM, DIM, 3*INNER, 3*INNER, nullptr, nullptr, 0, 1.f, 0);

        // scores = q @ k^T * scale  (batched over 96 batch-heads)
        {
            dim3 grid((SEQ + 127)/128, (SEQ + 127)/128, BATCH*HEADS);
            gemm_kernel<128,8,true><<<grid, 256>>>(
                pqkv,                  // q
                pqkv + INNER,          // k
                pattn,
                SEQ, SEQ, DH,
                3*INNER, 3*INNER, SEQ,
                HEADS,
                (long long)SEQ*3*INNER, (long long)DH,      // A: per-batch, per-head
                (long long)SEQ*3*INNER, (long long)DH,      // B
                (long long)HEADS*SEQ*SEQ, (long long)SEQ*SEQ,
                nullptr, nullptr, 0, scale, 0);
        }
        softmax_kernel<<<BATCH*HEADS*SEQ, 256>>>(pattn);
        // o = attn @ v  (BN=64 tile: exact fit for DH=64)
        {
            dim3 grid(1, (SEQ + 127)/128, BATCH*HEADS);
            gemm_kernel<64,4,false><<<grid, 256>>>(
                pattn,
                pqkv + 2*INNER,        // v
                po,
                SEQ, DH, SEQ,
                SEQ, 3*INNER, INNER,
                HEADS,
                (long long)HEADS*SEQ*SEQ, (long long)SEQ*SEQ,
                (long long)SEQ*3*INNER, (long long)DH,
                (long long)SEQ*INNER, (long long)DH,
                nullptr, nullptr, 0, 1.f, 0);
        }
        // x = o @ w_out + b_out + x
        gemm_flat(po, w_out + (long long)i*INNER*DIM, px,
                  TOK, DIM, INNER, INNER, DIM, DIM,
                  b_out + i*DIM, px, DIM, 1.f, 0);

        // ---- MLP ----
        layernorm_kernel<<<TOK, 128>>>(px, ph, ln2_g + i*DIM, ln2_b + i*DIM);
        gemm_flat(ph, w_ff1 + (long long)i*DIM*MLP, pff,
                  TOK, MLP, DIM, DIM, MLP, MLP,
                  b_ff1 + i*MLP, nullptr, 0, 1.f, 1 /*gelu*/);
        gemm_flat(pff, w_ff2 + (long long)i*MLP*DIM, px,
                  TOK, DIM, MLP, MLP, DIM, DIM,
                  b_ff2 + i*DIM, px, DIM, 1.f, 0);
    }

    copyout_kernel<<<(BATCH*DIM + 255)/256, 256>>>(px, out);
}

// round 4
// speedup vs baseline: 1.4892x; 1.4892x over previous
#include <cuda_runtime.h>
#include <math.h>
#include <stdint.h>

#define BATCH 16
#define CH 3
#define IMGSZ 384
#define PSZ 16
#define HP (IMGSZ/PSZ)          /* 24 */
#define DIM 384
#define DEPTH 6
#define HEADS 6
#define DH 64
#define INNER 384
#define MLP 1536
#define NPATCH 576
#define PATCH_DIM 768
#define SEQ 1153
#define TOK (BATCH*SEQ)         /* 18448 */

// ---------------- scratch (device globals: allocation-free rule) -------------
__device__ float g_x[(size_t)TOK*DIM];
__device__ float g_h[(size_t)TOK*DIM];
__device__ float g_qkv[(size_t)TOK*3*INNER];
__device__ float g_attn[(size_t)BATCH*HEADS*SEQ*SEQ];   // ~510 MB
__device__ float g_o[(size_t)TOK*INNER];
__device__ float g_ff[(size_t)TOK*MLP];
__device__ float g_patch[(size_t)BATCH*2*NPATCH*PATCH_DIM];

__device__ __forceinline__ uint32_t f2tf32(float x) {
    uint32_t r;
    asm("cvt.rna.tf32.f32 %0, %1;" : "=r"(r) : "f"(x));
    return r;
}

// ---------------- tf32 mma.sync GEMM -----------------------------------------
// C[M,N] = act(alpha * A@B (+bias)) (+residual)
// TRANSB=false: B is [K,N] row-major (ldb). TRANSB=true: B is [N,K] (ldb), C=A@B^T.
// Batched via grid.z: bz -> (outer = bz/innerCount, inner = bz%innerCount).
// Block tile BM x BN x 32, warp tile 64x32, mma m16n8k8 tf32.
template<int BM, int BN, bool TRANSB>
__global__ __launch_bounds__((BM/64)*(BN/32)*32) void mma_gemm(
    const float* __restrict__ A, const float* __restrict__ Bm, float* __restrict__ C,
    int M, int N, int K, int lda, int ldb, int ldc,
    int innerCount,
    long long aOuter, long long aInner,
    long long bOuter, long long bInner,
    long long cOuter, long long cInner,
    const float* __restrict__ bias,
    const float* __restrict__ resid, int ldr,
    float alpha, int act)
{
    constexpr int BK = 32;
    constexpr int WARPS_M = BM / 64;
    constexpr int WARPS_N = BN / 32;
    constexpr int NT = WARPS_M * WARPS_N * 32;

    __shared__ float As[BK][BM + 1];
    __shared__ float Bs[BK][BN + 4];

    const int bz = blockIdx.z;
    const int ob = bz / innerCount, ib = bz % innerCount;
    A  += ob*aOuter + ib*aInner;
    Bm += ob*bOuter + ib*bInner;
    C  += ob*cOuter + ib*cInner;
    const float* R = resid;
    if (R) R += ob*cOuter + ib*cInner;

    const int m0 = blockIdx.y * BM;
    const int n0 = blockIdx.x * BN;
    const int tid  = threadIdx.x;
    const int warp = tid >> 5;
    const int lane = tid & 31;
    const int warpM = warp / WARPS_N;
    const int warpN = warp % WARPS_N;
    const int gID = lane >> 2;      // group id 0..7
    const int tig = lane & 3;       // thread-in-group 0..3

    const bool vecA = ((lda & 3) == 0);
    const bool vecB = ((ldb & 3) == 0);

    float acc[4][4][4];
    #pragma unroll
    for (int a = 0; a < 4; a++)
        #pragma unroll
        for (int b = 0; b < 4; b++)
            #pragma unroll
            for (int c = 0; c < 4; c++) acc[a][b][c] = 0.f;

    for (int k0 = 0; k0 < K; k0 += BK) {
        const bool fullA = (m0 + BM <= M) && (k0 + BK <= K);
        const bool fullB = TRANSB ? ((n0 + BN <= N) && (k0 + BK <= K))
                                  : ((k0 + BK <= K) && (n0 + BN <= N));
        // ---- load A tile: As[k][m] = A[m0+m][k0+k]
        #pragma unroll
        for (int i = tid; i < BM * (BK/4); i += NT) {
            int m  = i / (BK/4);
            int kq = (i % (BK/4)) * 4;
            float4 v = make_float4(0.f, 0.f, 0.f, 0.f);
            int gm = m0 + m;
            if (fullA && vecA) {
                v = *reinterpret_cast<const float4*>(A + (long long)gm*lda + k0 + kq);
            } else if (gm < M) {
                const float* ap = A + (long long)gm*lda + k0 + kq;
                if (k0 + kq + 0 < K) v.x = ap[0];
                if (k0 + kq + 1 < K) v.y = ap[1];
                if (k0 + kq + 2 < K) v.z = ap[2];
                if (k0 + kq + 3 < K) v.w = ap[3];
            }
            As[kq+0][m] = v.x; As[kq+1][m] = v.y;
            As[kq+2][m] = v.z; As[kq+3][m] = v.w;
        }
        // ---- load B tile: Bs[k][n]
        if (!TRANSB) {
            #pragma unroll
            for (int i = tid; i < BK * (BN/4); i += NT) {
                int k  = i / (BN/4);
                int nq = (i % (BN/4)) * 4;
                float4 v = make_float4(0.f, 0.f, 0.f, 0.f);
                int gk = k0 + k;
                if (fullB && vecB) {
                    v = *reinterpret_cast<const float4*>(Bm + (long long)gk*ldb + n0 + nq);
                } else if (gk < K) {
                    const float* bp = Bm + (long long)gk*ldb + n0 + nq;
                    if (n0 + nq + 0 < N) v.x = bp[0];
                    if (n0 + nq + 1 < N) v.y = bp[1];
                    if (n0 + nq + 2 < N) v.z = bp[2];
                    if (n0 + nq + 3 < N) v.w = bp[3];
                }
                *reinterpret_cast<float4*>(&Bs[k][nq]) = v;
            }
        } else {
            #pragma unroll
            for (int i = tid; i < BN * (BK/4); i += NT) {
                int n  = i / (BK/4);
                int kq = (i % (BK/4)) * 4;
                float4 v = make_float4(0.f, 0.f, 0.f, 0.f);
                int gn = n0 + n;
                if (fullB && vecB) {
                    v = *reinterpret_cast<const float4*>(Bm + (long long)gn*ldb + k0 + kq);
                } else if (gn < N) {
                    const float* bp = Bm + (long long)gn*ldb + k0 + kq;
                    if (k0 + kq + 0 < K) v.x = bp[0];
                    if (k0 + kq + 1 < K) v.y = bp[1];
                    if (k0 + kq + 2 < K) v.z = bp[2];
                    if (k0 + kq + 3 < K) v.w = bp[3];
                }
                Bs[kq+0][n] = v.x; Bs[kq+1][n] = v.y;
                Bs[kq+2][n] = v.z; Bs[kq+3][n] = v.w;
            }
        }
        __syncthreads();

        // ---- compute: 4 k-slices of 8
        #pragma unroll
        for (int ks = 0; ks < 4; ks++) {
            uint32_t af[4][4], bf[4][2];
            #pragma unroll
            for (int mi = 0; mi < 4; mi++) {
                int mb = warpM*64 + mi*16;
                af[mi][0] = f2tf32(As[ks*8 + tig    ][mb + gID    ]);
                af[mi][1] = f2tf32(As[ks*8 + tig    ][mb + gID + 8]);
                af[mi][2] = f2tf32(As[ks*8 + tig + 4][mb + gID    ]);
                af[mi][3] = f2tf32(As[ks*8 + tig + 4][mb + gID + 8]);
            }
            #pragma unroll
            for (int ni = 0; ni < 4; ni++) {
                int nb = warpN*32 + ni*8;
                bf[ni][0] = f2tf32(Bs[ks*8 + tig    ][nb + gID]);
                bf[ni][1] = f2tf32(Bs[ks*8 + tig + 4][nb + gID]);
            }
            #pragma unroll
            for (int mi = 0; mi < 4; mi++)
                #pragma unroll
                for (int ni = 0; ni < 4; ni++) {
                    asm volatile(
                        "mma.sync.aligned.m16n8k8.row.col.f32.tf32.tf32.f32 "
                        "{%0,%1,%2,%3}, {%4,%5,%6,%7}, {%8,%9}, {%0,%1,%2,%3};"
                        : "+f"(acc[mi][ni][0]), "+f"(acc[mi][ni][1]),
                          "+f"(acc[mi][ni][2]), "+f"(acc[mi][ni][3])
                        : "r"(af[mi][0]), "r"(af[mi][1]), "r"(af[mi][2]), "r"(af[mi][3]),
                          "r"(bf[ni][0]), "r"(bf[ni][1]));
                }
        }
        __syncthreads();
    }

    // ---- epilogue
    #pragma unroll
    for (int mi = 0; mi < 4; mi++) {
        int r0 = m0 + warpM*64 + mi*16 + gID;
        int r1 = r0 + 8;
        #pragma unroll
        for (int ni = 0; ni < 4; ni++) {
            int cc = n0 + warpN*32 + ni*8 + tig*2;
            #pragma unroll
            for (int e = 0; e < 4; e++) {
                int m = (e < 2) ? r0 : r1;
                int n = cc + (e & 1);
                if (m < M && n < N) {
                    float v = acc[mi][ni][e] * alpha;
                    if (bias) v += bias[n];
                    if (act)  v = 0.5f * v * (1.f + erff(v * 0.70710678118654752440f));
                    if (R)    v += R[(long long)m*ldr + n];
                    C[(long long)m*ldc + n] = v;
                }
            }
        }
    }
}

// ---------------- patchify: img -> [b, t(0..1151), 768] ---------------------
__global__ void patchify_kernel(const float* __restrict__ before,
                                const float* __restrict__ after,
                                float* __restrict__ out)
{
    long long idx = (long long)blockIdx.x * blockDim.x + threadIdx.x;
    const long long total = (long long)BATCH * 2 * NPATCH * PATCH_DIM;
    if (idx >= total) return;
    int pd = (int)(idx % PATCH_DIM);
    long long tmp = idx / PATCH_DIM;
    int t = (int)(tmp % (2*NPATCH));
    int b = (int)(tmp / (2*NPATCH));
    const float* img = (t < NPATCH) ? before : after;
    int tt = t % NPATCH;
    int hh = tt / HP, ww = tt % HP;
    int c = pd % CH;
    int q = pd / CH;
    int p2 = q % PSZ, p1 = q / PSZ;
    out[idx] = img[((long long)b*CH + c)*IMGSZ*IMGSZ + (long long)(hh*PSZ + p1)*IMGSZ + (ww*PSZ + p2)];
}

// ---------------- assemble x = [cls | emb+pos | emb+pos] ---------------------
__global__ void assemble_kernel(const float* __restrict__ emb,
                                const float* __restrict__ pos,
                                const float* __restrict__ cls,
                                float* __restrict__ x)
{
    long long idx = (long long)blockIdx.x * blockDim.x + threadIdx.x;
    const long long total = (long long)TOK * DIM;
    if (idx >= total) return;
    int d = (int)(idx % DIM);
    long long tmp = idx / DIM;
    int s = (int)(tmp % SEQ);
    int b = (int)(tmp / SEQ);
    float v;
    if (s == 0) v = cls[d];
    else {
        int t = s - 1;
        v = emb[((long long)b*(2*NPATCH) + t)*DIM + d] + pos[(long long)(t % NPATCH)*DIM + d];
    }
    x[idx] = v;
}

// ---------------- LayerNorm (row of 384, 128 threads/row) --------------------
__global__ __launch_bounds__(128) void layernorm_kernel(
    const float* __restrict__ x, float* __restrict__ y,
    const float* __restrict__ g, const float* __restrict__ bta)
{
    long long row = blockIdx.x;
    const float* xr = x + row * DIM;
    int t = threadIdx.x;
    float v0 = xr[t], v1 = xr[t+128], v2 = xr[t+256];
    float s  = v0 + v1 + v2;
    float s2 = v0*v0 + v1*v1 + v2*v2;
    #pragma unroll
    for (int o = 16; o; o >>= 1) {
        s  += __shfl_xor_sync(0xffffffffu, s,  o);
        s2 += __shfl_xor_sync(0xffffffffu, s2, o);
    }
    __shared__ float sh[8];
    int w = t >> 5;
    if ((t & 31) == 0) { sh[w] = s; sh[4+w] = s2; }
    __syncthreads();
    s  = sh[0] + sh[1] + sh[2] + sh[3];
    s2 = sh[4] + sh[5] + sh[6] + sh[7];
    float mean = s * (1.f/DIM);
    float var  = s2 * (1.f/DIM) - mean*mean;
    float r = rsqrtf(var + 1e-5f);
    float* yr = y + row * DIM;
    yr[t]     = (v0 - mean)*r*g[t]     + bta[t];
    yr[t+128] = (v1 - mean)*r*g[t+128] + bta[t+128];
    yr[t+256] = (v2 - mean)*r*g[t+256] + bta[t+256];
}

// ---------------- row softmax over SEQ=1153 ----------------------------------
__global__ __launch_bounds__(256) void softmax_kernel(float* __restrict__ a)
{
    long long row = blockIdx.x;
    float* ar = a + row * (long long)SEQ;
    int t = threadIdx.x;
    float vals[5];
    float mx = -3.0e38f;
    #pragma unroll
    for (int i = 0; i < 5; i++) {
        int j = t + i*256;
        vals[i] = (j < SEQ) ? ar[j] : -3.0e38f;
        mx = fmaxf(mx, vals[i]);
    }
    __shared__ float sh[8];
    #pragma unroll
    for (int o = 16; o; o >>= 1) mx = fmaxf(mx, __shfl_xor_sync(0xffffffffu, mx, o));
    if ((t & 31) == 0) sh[t >> 5] = mx;
    __syncthreads();
    mx = fmaxf(fmaxf(fmaxf(sh[0],sh[1]),fmaxf(sh[2],sh[3])),
               fmaxf(fmaxf(sh[4],sh[5]),fmaxf(sh[6],sh[7])));
    __syncthreads();
    float s = 0.f;
    #pragma unroll
    for (int i = 0; i < 5; i++) {
        int j = t + i*256;
        vals[i] = (j < SEQ) ? expf(vals[i] - mx) : 0.f;
        s += vals[i];
    }
    #pragma unroll
    for (int o = 16; o; o >>= 1) s += __shfl_xor_sync(0xffffffffu, s, o);
    if ((t & 31) == 0) sh[t >> 5] = s;
    __syncthreads();
    s = sh[0]+sh[1]+sh[2]+sh[3]+sh[4]+sh[5]+sh[6]+sh[7];
    float inv = 1.f / s;
    #pragma unroll
    for (int i = 0; i < 5; i++) {
        int j = t + i*256;
        if (j < SEQ) ar[j] = vals[i] * inv;
    }
}

// ---------------- output: cls rows -------------------------------------------
__global__ void copyout_kernel(const float* __restrict__ x, float* __restrict__ out)
{
    int idx = blockIdx.x * blockDim.x + threadIdx.x;
    if (idx >= BATCH * DIM) return;
    int b = idx / DIM, d = idx % DIM;
    out[idx] = x[(long long)b*SEQ*DIM + d];
}

// ---------------- host orchestration -----------------------------------------
static inline void gemm_flat(const float* A, const float* Bm, float* C,
                             int M, int N, int K, int lda, int ldb, int ldc,
                             const float* bias, const float* resid, int ldr,
                             float alpha, int act)
{
    dim3 grid((N + 127) / 128, (M + 127) / 128, 1);
    mma_gemm<128,128,false><<<grid, 256>>>(A, Bm, C, M, N, K, lda, ldb, ldc,
        1, 0, 0, 0, 0, 0, 0, bias, resid, ldr, alpha, act);
}

extern "C" void kernel_launch(void* const* d_in, const int* in_sizes, int n_in,
                              void* d_out, int out_size)
{
    const float* img_before = (const float*)d_in[0];
    const float* img_after  = (const float*)d_in[1];
    const float* patch_w    = (const float*)d_in[2];
    const float* patch_b    = (const float*)d_in[3];
    const float* pos_emb    = (const float*)d_in[4];
    const float* cls_tok    = (const float*)d_in[5];
    const float* ln1_g      = (const float*)d_in[6];
    const float* ln1_b      = (const float*)d_in[7];
    const float* w_qkv      = (const float*)d_in[8];
    const float* w_out      = (const float*)d_in[9];
    const float* b_out      = (const float*)d_in[10];
    const float* ln2_g      = (const float*)d_in[11];
    const float* ln2_b      = (const float*)d_in[12];
    const float* w_ff1      = (const float*)d_in[13];
    const float* b_ff1      = (const float*)d_in[14];
    const float* w_ff2      = (const float*)d_in[15];
    const float* b_ff2      = (const float*)d_in[16];
    float* out = (float*)d_out;

    static float *px=nullptr, *ph=nullptr, *pqkv=nullptr, *pattn=nullptr,
                 *po=nullptr, *pff=nullptr, *ppatch=nullptr;
    if (!px) {
        cudaGetSymbolAddress((void**)&px,    g_x);
        cudaGetSymbolAddress((void**)&ph,    g_h);
        cudaGetSymbolAddress((void**)&pqkv,  g_qkv);
        cudaGetSymbolAddress((void**)&pattn, g_attn);
        cudaGetSymbolAddress((void**)&po,    g_o);
        cudaGetSymbolAddress((void**)&pff,   g_ff);
        cudaGetSymbolAddress((void**)&ppatch,g_patch);
    }

    // ---- patch embedding ----
    {
        long long total = (long long)BATCH * 2 * NPATCH * PATCH_DIM;
        patchify_kernel<<<(unsigned)((total + 255) / 256), 256>>>(img_before, img_after, ppatch);
        gemm_flat(ppatch, patch_w, po, BATCH*2*NPATCH, DIM, PATCH_DIM,
                  PATCH_DIM, DIM, DIM, patch_b, nullptr, 0, 1.f, 0);
        long long tx = (long long)TOK * DIM;
        assemble_kernel<<<(unsigned)((tx + 255) / 256), 256>>>(po, pos_emb, cls_tok, px);
    }

    const float scale = 0.125f;   // DH^-0.5

    for (int i = 0; i < DEPTH; i++) {
        // ---- attention ----
        layernorm_kernel<<<TOK, 128>>>(px, ph, ln1_g + i*DIM, ln1_b + i*DIM);
        gemm_flat(ph, w_qkv + (long long)i*DIM*3*INNER, pqkv,
                  TOK, 3*INNER, DIM, DIM, 3*INNER, 3*INNER, nullptr, nullptr, 0, 1.f, 0);

        // scores = q @ k^T * scale  (batched over 96 batch-heads)
        {
            dim3 grid((SEQ + 127)/128, (SEQ + 127)/128, BATCH*HEADS);
            mma_gemm<128,128,true><<<grid, 256>>>(
                pqkv,                  // q
                pqkv + INNER,          // k
                pattn,
                SEQ, SEQ, DH,
                3*INNER, 3*INNER, SEQ,
                HEADS,
                (long long)SEQ*3*INNER, (long long)DH,
                (long long)SEQ*3*INNER, (long long)DH,
                (long long)HEADS*SEQ*SEQ, (long long)SEQ*SEQ,
                nullptr, nullptr, 0, scale, 0);
        }
        softmax_kernel<<<BATCH*HEADS*SEQ, 256>>>(pattn);
        // o = attn @ v  (BN=64: exact fit for DH=64)
        {
            dim3 grid(1, (SEQ + 127)/128, BATCH*HEADS);
            mma_gemm<128,64,false><<<grid, 128>>>(
                pattn,
                pqkv + 2*INNER,        // v
                po,
                SEQ, DH, SEQ,
                SEQ, 3*INNER, INNER,
                HEADS,
                (long long)HEADS*SEQ*SEQ, (long long)SEQ*SEQ,
                (long long)SEQ*3*INNER, (long long)DH,
                (long long)SEQ*INNER, (long long)DH,
                nullptr, nullptr, 0, 1.f, 0);
        }
        // x = o @ w_out + b_out + x
        gemm_flat(po, w_out + (long long)i*INNER*DIM, px,
                  TOK, DIM, INNER, INNER, DIM, DIM,
                  b_out + i*DIM, px, DIM, 1.f, 0);

        // ---- MLP ----
        layernorm_kernel<<<TOK, 128>>>(px, ph, ln2_g + i*DIM, ln2_b + i*DIM);
        gemm_flat(ph, w_ff1 + (long long)i*DIM*MLP, pff,
                  TOK, MLP, DIM, DIM, MLP, MLP,
                  b_ff1 + i*MLP, nullptr, 0, 1.f, 1 /*gelu*/);
        gemm_flat(pff, w_ff2 + (long long)i*MLP*DIM, px,
                  TOK, DIM, MLP, MLP, DIM, DIM,
                  b_ff2 + i*DIM, px, DIM, 1.f, 0);
    }

    copyout_kernel<<<(BATCH*DIM + 255)/256, 256>>>(px, out);
}